// round 5
// baseline (speedup 1.0000x reference)
#include <cuda_runtime.h>

// WeightedDistanceTransform — single fused kernel.
// 16 strip-CTAs per slice; ticket/epoch gmem barriers (replay-safe, no resets).
// Flow per CTA: pack mask for 16 rows -> barrier A -> g^2 on the fly (clz/ffs)
// -> exact vertical min-plus (early exit), dt in registers -> strip max ->
// barrier B -> slice max -> normalized single output write.

#define HH 256
#define WW 256
#define NPIX (HH * WW)
#define BIG 512
#define MAXSLICES 64
#define WPR 8                       // 32-bit mask words per row
#define NTH 256
#define PXT 16                      // pixels per thread (strip: 256 rows x 16 cols)

__device__ unsigned int maskbuf[MAXSLICES * HH * WPR];   // 2 KB per slice
__device__ float        smax_g[MAXSLICES * 16];
__device__ unsigned int ctrA[MAXSLICES];                  // monotonic, zero-init
__device__ unsigned int ctrB[MAXSLICES];

__device__ __forceinline__ void slice_barrier(unsigned int* ctr, int tid) {
    if (tid == 0) {
        __threadfence();
        unsigned t = atomicAdd(ctr, 1u);
        unsigned target = ((t >> 4) + 1u) << 4;            // 16 arrivals per epoch
        while (atomicAdd(ctr, 0u) < target) __nanosleep(32);
        __threadfence();
    }
    __syncthreads();
}

__global__ __launch_bounds__(NTH, 6)
void wdt_fused(const float* __restrict__ in, float* __restrict__ out) {
    __shared__ unsigned int M[HH * WPR];          // 2 KB whole-slice bitmask
    __shared__ unsigned int g2[HH * 16];          // 16 KB g^2 tile [row][col]
    __shared__ float red[NTH / 32];
    __shared__ float mxsh;

    const int slice = blockIdx.x >> 4;
    const int st    = blockIdx.x & 15;
    const int c0    = st * 16;
    const int tid   = threadIdx.x;

    // ---- Phase 1: pack mask for rows [16*st, 16*st+16) ----
    {
        const float4* s4 = reinterpret_cast<const float4*>(in)
                         + (size_t)slice * (NPIX / 4) + (size_t)st * 1024 + tid * 4;
        float4 a = s4[0], b = s4[1], c = s4[2], d = s4[3];
        unsigned m = 0;
        m |= (a.x != 0.0f) << 0;  m |= (a.y != 0.0f) << 1;
        m |= (a.z != 0.0f) << 2;  m |= (a.w != 0.0f) << 3;
        m |= (b.x != 0.0f) << 4;  m |= (b.y != 0.0f) << 5;
        m |= (b.z != 0.0f) << 6;  m |= (b.w != 0.0f) << 7;
        m |= (c.x != 0.0f) << 8;  m |= (c.y != 0.0f) << 9;
        m |= (c.z != 0.0f) << 10; m |= (c.w != 0.0f) << 11;
        m |= (d.x != 0.0f) << 12; m |= (d.y != 0.0f) << 13;
        m |= (d.z != 0.0f) << 14; m |= (d.w != 0.0f) << 15;
        unsigned other = __shfl_xor_sync(0xffffffffu, m, 1);
        if ((tid & 1) == 0)
            maskbuf[slice * (HH * WPR) + st * 128 + (tid >> 1)] = m | (other << 16);
    }

    // ---- Barrier A: slice mask complete ----
    slice_barrier(&ctrA[slice], tid);

    // ---- Phase 2: load slice mask to smem ----
    {
        const unsigned int* src = maskbuf + slice * (HH * WPR);
        #pragma unroll
        for (int k = 0; k < (HH * WPR) / NTH; ++k)
            M[k * NTH + tid] = src[k * NTH + tid];
    }
    __syncthreads();

    // ---- Phase 3: g^2 for the strip (cols c0..c0+15, all rows) ----
    #pragma unroll
    for (int it = 0; it < PXT; ++it) {
        int i = it * NTH + tid;
        int r = i >> 4;
        int w = c0 + (i & 15);
        const unsigned int* Mr = M + r * WPR;
        int ci = w >> 5, b = w & 31;

        int ld = BIG;                                          // nearest zero <= w
        unsigned lmask = (b == 31) ? 0xffffffffu : ((2u << b) - 1u);
        unsigned z = (~Mr[ci]) & lmask;
        if (z) {
            ld = b - (31 - __clz(z));
        } else {
            for (int cj = ci - 1; cj >= 0; --cj) {
                unsigned zz = ~Mr[cj];
                if (zz) { ld = (ci - cj) * 32 + b - (31 - __clz(zz)); break; }
            }
        }
        int rd = BIG;                                          // nearest zero >= w
        z = (~Mr[ci]) >> b;
        if (z) {
            rd = __ffs(z) - 1;
        } else {
            for (int cj = ci + 1; cj < WPR; ++cj) {
                unsigned zz = ~Mr[cj];
                if (zz) { rd = cj * 32 + (__ffs(zz) - 1) - w; break; }
            }
        }
        int g = min(min(ld, rd), BIG);
        g2[r * 16 + (i & 15)] = (unsigned)(g * g);
    }
    __syncthreads();

    // ---- Phase 4: vertical min-plus, dt in registers ----
    const float wts[3] = {0.5f, 1.0f, 2.0f};
    const float wc = wts[slice % 3];

    float dt[PXT];
    float lmax = 0.0f;
    #pragma unroll
    for (int it = 0; it < PXT; ++it) {
        int i = it * NTH + tid;
        int r = i >> 4, c = i & 15;
        int best = (int)g2[r * 16 + c];
        for (int d = 1; d < HH; ++d) {
            int dd = d * d;
            if (dd >= best) break;                // exact: candidates >= d^2
            int up = r - d, dn = r + d;
            if (up >= 0) best = min(best, (int)g2[up * 16 + c] + dd);
            if (dn < HH) best = min(best, (int)g2[dn * 16 + c] + dd);
        }
        float v = wc * sqrtf((float)best);
        dt[it] = v;
        lmax = fmaxf(lmax, v);
    }

    // ---- strip max -> gmem ----
    #pragma unroll
    for (int o = 16; o; o >>= 1) lmax = fmaxf(lmax, __shfl_xor_sync(0xffffffffu, lmax, o));
    if ((tid & 31) == 0) red[tid >> 5] = lmax;
    __syncthreads();
    if (tid < 8) {
        float v = red[tid];
        #pragma unroll
        for (int o = 4; o; o >>= 1) v = fmaxf(v, __shfl_xor_sync(0x000000ffu, v, o));
        if (tid == 0) smax_g[slice * 16 + st] = v;   // plain store, overwritten each replay
    }

    // ---- Barrier B: all strip maxima visible ----
    slice_barrier(&ctrB[slice], tid);

    // ---- slice max reduce (16 values) ----
    if (tid < 16) {
        float v = smax_g[slice * 16 + tid];
        #pragma unroll
        for (int o = 8; o; o >>= 1) v = fmaxf(v, __shfl_xor_sync(0x0000ffffu, v, o, 16));
        if (tid == 0) mxsh = v;
    }
    __syncthreads();

    const float mx  = mxsh;
    const float inv = (mx > 0.0f) ? (1.0f / mx) : 0.0f;   // mx==0 -> dt==0 -> out 0

    // ---- Phase 5: normalize + single output write ----
    float* dst = out + (size_t)slice * NPIX;
    #pragma unroll
    for (int it = 0; it < PXT; ++it) {
        int i = it * NTH + tid;
        int r = i >> 4, c = i & 15;
        dst[r * WW + c0 + c] = (mx - dt[it]) * inv;
    }
}

extern "C" void kernel_launch(void* const* d_in, const int* in_sizes, int n_in,
                              void* d_out, int out_size) {
    const float* in = (const float*)d_in[0];
    float* out = (float*)d_out;
    const int nslices = in_sizes[0] / NPIX;       // 48 for [16,3,256,256]
    wdt_fused<<<nslices * 16, NTH>>>(in, out);
}

// round 6
// speedup vs baseline: 1.1109x; 1.1109x over previous
#include <cuda_runtime.h>

// WeightedDistanceTransform — 3-kernel pipeline (R4 structure, tuned k1/k2).
// k1: coalesced float4 stream + shuffle-pack -> 1-bit mask (8 KB/slice)
// k2: g^2 on the fly (clz/ffs) into padded smem tile; vertical min-plus with
//     branch-free d=1..3 (register window) + rare exact escape loop;
//     dt write + per-slice atomicMax.
// k3: inverted normalize (mx - dt)/mx.

#define HH 256
#define WW 256
#define NPIX (HH * WW)
#define BIG 512
#define MAXSLICES 64
#define WPR 8                        // mask words per row
#define SLICE_WORDS (HH * WPR)       // 2048
#define BIGVAL (1 << 28)

__device__ unsigned int maskbuf[MAXSLICES * SLICE_WORDS];
__device__ unsigned int mx_bits[MAXSLICES];

// ---------------- Kernel 1: mask pack (coalesced + shuffle-pack) ----------------
#define K1_THREADS 256

__global__ __launch_bounds__(K1_THREADS)
void k1_mask(const float* __restrict__ in) {
    // grid = nslices*16; CTA covers 16 rows = 4096 px
    const int slice = blockIdx.x >> 4;
    const int rb    = blockIdx.x & 15;
    const int tid   = threadIdx.x;
    const int lane  = tid & 31;
    const int warp  = tid >> 5;

    if (rb == 0 && tid == 0) mx_bits[slice] = 0u;   // reset before k2

    const float4* s4 = reinterpret_cast<const float4*>(in)
                     + (size_t)slice * (NPIX / 4) + (size_t)rb * 1024;
    unsigned int* wb = maskbuf + slice * SLICE_WORDS + rb * 128;

    #pragma unroll
    for (int j = 0; j < 4; ++j) {
        float4 v = s4[j * 256 + tid];               // fully coalesced
        unsigned nib = (unsigned)(v.x != 0.0f)
                     | ((unsigned)(v.y != 0.0f) << 1)
                     | ((unsigned)(v.z != 0.0f) << 2)
                     | ((unsigned)(v.w != 0.0f) << 3);
        unsigned sh = nib << ((lane & 7) * 4);
        sh |= __shfl_xor_sync(0xffffffffu, sh, 1);
        sh |= __shfl_xor_sync(0xffffffffu, sh, 2);
        sh |= __shfl_xor_sync(0xffffffffu, sh, 4);
        if ((lane & 7) == 0)
            wb[j * 32 + warp * 4 + (lane >> 3)] = sh;   // word = px>>5
    }
}

// ---------------- Kernel 2: g^2 + vertical min-plus ----------------
#define K2_THREADS 256
#define PAD 4
#define TS 17                         // padded tile row stride (words)

__global__ __launch_bounds__(K2_THREADS)
void k2_passB(float* __restrict__ out) {
    __shared__ unsigned int M[SLICE_WORDS];              // 8 KB slice bitmask
    __shared__ unsigned int g2t[(HH + 2 * PAD) * TS];    // ~17.9 KB padded g^2 tile
    __shared__ float red[K2_THREADS / 32];

    const int slice = blockIdx.x >> 4;                   // 16 strips/slice
    const int st    = blockIdx.x & 15;
    const int c0    = st * 16;
    const int tid   = threadIdx.x;

    // load slice bitmask (coalesced, 8 words/thread)
    {
        const unsigned int* src = maskbuf + slice * SLICE_WORDS;
        #pragma unroll
        for (int k = 0; k < SLICE_WORDS / K2_THREADS; ++k)
            M[k * K2_THREADS + tid] = src[k * K2_THREADS + tid];
    }
    // fill pad rows with BIGVAL (never wins)
    for (int idx = tid; idx < 2 * PAD * TS; idx += K2_THREADS) {
        int rr = idx / TS, cc = idx % TS;
        int row = (rr < PAD) ? rr : rr + HH;
        g2t[row * TS + cc] = BIGVAL;
    }
    __syncthreads();

    // g^2 for the strip via clz/ffs on row bitmask (16 px/thread)
    #pragma unroll
    for (int it = 0; it < 16; ++it) {
        int i = it * K2_THREADS + tid;
        int r = i >> 4;
        int w = c0 + (i & 15);
        const unsigned int* Mr = M + r * WPR;
        int ci = w >> 5, b = w & 31;

        int ld = BIG;                                    // nearest zero <= w
        unsigned lmask = (b == 31) ? 0xffffffffu : ((2u << b) - 1u);
        unsigned z = (~Mr[ci]) & lmask;
        if (z) {
            ld = b - (31 - __clz(z));
        } else {
            for (int cj = ci - 1; cj >= 0; --cj) {
                unsigned zz = ~Mr[cj];
                if (zz) { ld = (ci - cj) * 32 + b - (31 - __clz(zz)); break; }
            }
        }
        int rd = BIG;                                    // nearest zero >= w
        z = (~Mr[ci]) >> b;
        if (z) {
            rd = __ffs(z) - 1;
        } else {
            for (int cj = ci + 1; cj < WPR; ++cj) {
                unsigned zz = ~Mr[cj];
                if (zz) { rd = cj * 32 + (__ffs(zz) - 1) - w; break; }
            }
        }
        int g = min(min(ld, rd), BIG);
        g2t[(r + PAD) * TS + (i & 15)] = (unsigned)(g * g);
    }
    __syncthreads();

    const float wts[3] = {0.5f, 1.0f, 2.0f};
    const float wc = wts[slice % 3];
    float* dst = out + (size_t)slice * NPIX;

    // each thread: one column (c), 16 consecutive rows [r0, r0+16)
    const int c  = tid & 15;
    const int r0 = (tid >> 4) * 16;

    unsigned w22[22];                                    // rows r0-3 .. r0+18
    #pragma unroll
    for (int j = 0; j < 22; ++j)
        w22[j] = g2t[(r0 + j + (PAD - 3)) * TS + c];

    float lmax = 0.0f;
    #pragma unroll
    for (int k = 0; k < 16; ++k) {
        int best = (int)w22[k + 3];
        best = min(best, (int)min(w22[k + 2], w22[k + 4]) + 1);
        best = min(best, (int)min(w22[k + 1], w22[k + 5]) + 4);
        best = min(best, (int)min(w22[k    ], w22[k + 6]) + 9);
        if (best > 16) {                                 // rare: exact escape
            int r = r0 + k;
            for (int d = 4; d * d < best; ++d) {
                int dd = d * d;
                int up = r - d, dn = r + d;
                bool any = false;
                if (up >= 0) { best = min(best, (int)g2t[(up + PAD) * TS + c] + dd); any = true; }
                if (dn < HH) { best = min(best, (int)g2t[(dn + PAD) * TS + c] + dd); any = true; }
                if (!any) break;
            }
        }
        float v = wc * sqrtf((float)best);
        dst[(r0 + k) * WW + c0 + c] = v;
        lmax = fmaxf(lmax, v);
    }

    // per-slice max
    #pragma unroll
    for (int o = 16; o; o >>= 1) lmax = fmaxf(lmax, __shfl_xor_sync(0xffffffffu, lmax, o));
    if ((tid & 31) == 0) red[tid >> 5] = lmax;
    __syncthreads();
    if (tid < 8) {
        float v = red[tid];
        #pragma unroll
        for (int o = 4; o; o >>= 1) v = fmaxf(v, __shfl_xor_sync(0x000000ffu, v, o));
        if (tid == 0) atomicMax(&mx_bits[slice], __float_as_uint(v));  // dt>=0: bit-monotone
    }
}

// ---------------- Kernel 3: normalize ----------------
#define K3_THREADS 256

__global__ __launch_bounds__(K3_THREADS)
void k3_norm(float* __restrict__ out) {
    const int slice = blockIdx.x >> 4;
    const int bl    = blockIdx.x & 15;
    const float mx  = __uint_as_float(mx_bits[slice]);
    const float inv = (mx > 0.0f) ? (1.0f / mx) : 0.0f;  // mx==0 -> dt==0 -> out 0

    float4* p = reinterpret_cast<float4*>(out) + (size_t)slice * (NPIX / 4) + bl * 1024;
    #pragma unroll
    for (int k = 0; k < 4; ++k) {
        int j = k * K3_THREADS + threadIdx.x;
        float4 v = p[j];
        v.x = (mx - v.x) * inv;
        v.y = (mx - v.y) * inv;
        v.z = (mx - v.z) * inv;
        v.w = (mx - v.w) * inv;
        p[j] = v;
    }
}

extern "C" void kernel_launch(void* const* d_in, const int* in_sizes, int n_in,
                              void* d_out, int out_size) {
    const float* in = (const float*)d_in[0];
    float* out = (float*)d_out;
    const int nslices = in_sizes[0] / NPIX;              // 48 for [16,3,256,256]

    k1_mask <<<nslices * 16, K1_THREADS>>>(in);
    k2_passB<<<nslices * 16, K2_THREADS>>>(out);
    k3_norm <<<nslices * 16, K3_THREADS>>>(out);
}

// round 7
// speedup vs baseline: 1.5188x; 1.3672x over previous
#include <cuda_runtime.h>

// WeightedDistanceTransform — 3-kernel pipeline (R4 structure; k2 at 512 threads).
// k1: bitmask pack (ballot) -> 1-bit mask scratch
// k2: g^2 on the fly? no — R4 scheme: g (u16) scratch-free: recompute from mask;
//     vertical min-plus with sound early exit -> dt + per-slice atomicMax
// k3: inverted normalize (mx - dt)/mx.

#define HH 256
#define WW 256
#define NPIX (HH * WW)
#define BIG 512
#define MAXSLICES 64
#define WPR 8
#define SLICE_WORDS (HH * WPR)        // 2048

__device__ unsigned int maskbuf[MAXSLICES * SLICE_WORDS];
__device__ unsigned int mx_bits[MAXSLICES];

// ---------------- Kernel 1: mask pack (R4 version, verbatim) ----------------
#define K1_THREADS 256

__global__ __launch_bounds__(K1_THREADS)
void k1_mask(const float* __restrict__ in) {
    const int slice = blockIdx.x >> 4;
    const int rb    = blockIdx.x & 15;
    const int tid   = threadIdx.x;

    if (rb == 0 && tid == 0) mx_bits[slice] = 0u;        // reset before k2

    const float4* s4 = reinterpret_cast<const float4*>(in)
                     + (size_t)slice * (NPIX / 4) + (size_t)rb * 1024 + tid * 4;
    float4 a = s4[0], b = s4[1], c = s4[2], d = s4[3];
    unsigned m = 0;
    m |= (a.x != 0.0f) << 0;  m |= (a.y != 0.0f) << 1;
    m |= (a.z != 0.0f) << 2;  m |= (a.w != 0.0f) << 3;
    m |= (b.x != 0.0f) << 4;  m |= (b.y != 0.0f) << 5;
    m |= (b.z != 0.0f) << 6;  m |= (b.w != 0.0f) << 7;
    m |= (c.x != 0.0f) << 8;  m |= (c.y != 0.0f) << 9;
    m |= (c.z != 0.0f) << 10; m |= (c.w != 0.0f) << 11;
    m |= (d.x != 0.0f) << 12; m |= (d.y != 0.0f) << 13;
    m |= (d.z != 0.0f) << 14; m |= (d.w != 0.0f) << 15;
    unsigned other = __shfl_xor_sync(0xffffffffu, m, 1);
    if ((tid & 1) == 0) {
        maskbuf[slice * SLICE_WORDS + rb * 128 + (tid >> 1)] = m | (other << 16);
    }
}

// ---------------- Kernel 2: g^2 on the fly + vertical min-plus (512 thr) ----------------
#define K2_COLS 16
#define K2_THREADS 512

__global__ __launch_bounds__(K2_THREADS)
void k2_passB(float* __restrict__ out) {
    __shared__ unsigned int M[SLICE_WORDS];       // 8 KB: whole-slice bitmask
    __shared__ unsigned int g2[HH * K2_COLS];     // 16 KB: g^2 tile [row][col]
    __shared__ float red[K2_THREADS / 32];        // 16 warps

    const int slice = blockIdx.x >> 4;            // 16 strips per slice
    const int st    = blockIdx.x & 15;
    const int c0    = st * K2_COLS;
    const int tid   = threadIdx.x;

    // load slice bitmask: 2048 words -> 4 words/thread
    {
        const unsigned int* src = maskbuf + slice * SLICE_WORDS;
        #pragma unroll
        for (int k = 0; k < SLICE_WORDS / K2_THREADS; ++k)
            M[k * K2_THREADS + tid] = src[k * K2_THREADS + tid];
    }
    __syncthreads();

    // compute g^2 for the strip: 8 px/thread via clz/ffs on row bitmask
    #pragma unroll
    for (int it = 0; it < (HH * K2_COLS) / K2_THREADS; ++it) {
        int i = it * K2_THREADS + tid;
        int r = i >> 4;
        int w = c0 + (i & 15);
        const unsigned int* Mr = M + r * WPR;
        int ci = w >> 5, b = w & 31;

        int ld = BIG;                                          // nearest zero <= w
        unsigned lmask = (b == 31) ? 0xffffffffu : ((2u << b) - 1u);
        unsigned z = (~Mr[ci]) & lmask;
        if (z) {
            ld = b - (31 - __clz(z));
        } else {
            for (int cj = ci - 1; cj >= 0; --cj) {
                unsigned zz = ~Mr[cj];
                if (zz) { ld = (ci - cj) * 32 + b - (31 - __clz(zz)); break; }
            }
        }
        int rd = BIG;                                          // nearest zero >= w
        z = (~Mr[ci]) >> b;
        if (z) {
            rd = __ffs(z) - 1;
        } else {
            for (int cj = ci + 1; cj < WPR; ++cj) {
                unsigned zz = ~Mr[cj];
                if (zz) { rd = cj * 32 + (__ffs(zz) - 1) - w; break; }
            }
        }
        int g = min(min(ld, rd), BIG);
        g2[r * K2_COLS + (i & 15)] = (unsigned)(g * g);
    }
    __syncthreads();

    const float wts[3] = {0.5f, 1.0f, 2.0f};
    const float wc = wts[slice % 3];
    float* dst = out + (size_t)slice * NPIX;

    float lmax = 0.0f;
    #pragma unroll
    for (int it = 0; it < (HH * K2_COLS) / K2_THREADS; ++it) {
        int i = it * K2_THREADS + tid;
        int r = i >> 4, c = i & 15;
        int best = (int)g2[r * K2_COLS + c];
        for (int d = 1; d < HH; ++d) {
            int dd = d * d;
            if (dd >= best) break;                // exact: candidates are >= d^2
            int up = r - d, dn = r + d;
            if (up >= 0) best = min(best, (int)g2[up * K2_COLS + c] + dd);
            if (dn < HH) best = min(best, (int)g2[dn * K2_COLS + c] + dd);
        }
        float dt = wc * sqrtf((float)best);
        dst[r * WW + c0 + c] = dt;
        lmax = fmaxf(lmax, dt);
    }

    #pragma unroll
    for (int o = 16; o; o >>= 1) lmax = fmaxf(lmax, __shfl_xor_sync(0xffffffffu, lmax, o));
    if ((tid & 31) == 0) red[tid >> 5] = lmax;
    __syncthreads();
    if (tid < 16) {
        float v = red[tid];
        #pragma unroll
        for (int o = 8; o; o >>= 1) v = fmaxf(v, __shfl_xor_sync(0x0000ffffu, v, o, 16));
        if (tid == 0) atomicMax(&mx_bits[slice], __float_as_uint(v));  // dt>=0: bit-monotone
    }
}

// ---------------- Kernel 3: normalize (R4 version, verbatim) ----------------
#define K3_THREADS 256

__global__ __launch_bounds__(K3_THREADS)
void k3_norm(float* __restrict__ out) {
    const int slice = blockIdx.x >> 4;
    const int bl    = blockIdx.x & 15;
    const float mx  = __uint_as_float(mx_bits[slice]);
    const float inv = (mx > 0.0f) ? (1.0f / mx) : 0.0f;   // mx==0 -> dt==0 -> out 0

    float4* p = reinterpret_cast<float4*>(out) + (size_t)slice * (NPIX / 4) + bl * 1024;
    #pragma unroll
    for (int k = 0; k < 4; ++k) {
        int j = k * K3_THREADS + threadIdx.x;
        float4 v = p[j];
        v.x = (mx - v.x) * inv;
        v.y = (mx - v.y) * inv;
        v.z = (mx - v.z) * inv;
        v.w = (mx - v.w) * inv;
        p[j] = v;
    }
}

extern "C" void kernel_launch(void* const* d_in, const int* in_sizes, int n_in,
                              void* d_out, int out_size) {
    const float* in = (const float*)d_in[0];
    float* out = (float*)d_out;
    const int nslices = in_sizes[0] / NPIX;       // 48 for [16,3,256,256]

    k1_mask <<<nslices * 16, K1_THREADS>>>(in);
    k2_passB<<<nslices * 16, K2_THREADS>>>(out);
    k3_norm <<<nslices * 16, K3_THREADS>>>(out);
}